// round 13
// baseline (speedup 1.0000x reference)
#include <cuda_runtime.h>
#include <math.h>

#define T_STEPS 2048
#define BATCH   32
#define HDIM    512
#define DIN     256
#define CSIZE   8      // CTAs per cluster
#define JSLICE  64     // j columns per CTA
#define RTHREADS 256

// ---- scratch (device globals; no allocation allowed) ----
__device__ float g_xw[(size_t)T_STEPS * HDIM * BATCH];   // [t][j][b], 134MB
__device__ float g_qh[BATCH * HDIM];                     // KW @ Q0
__device__ float g_sc[BATCH * T_STEPS];                  // scores
__device__ float g_att[BATCH * T_STEPS];                 // softmax weights
__device__ float g_cpart[8][BATCH * HDIM];               // context partials

// ---------------------------------------------------------------------------
__global__ void init_kernel() {
    int idx = blockIdx.x * blockDim.x + threadIdx.x;
    if (idx < BATCH * HDIM) g_qh[idx] = 0.f;
}

__global__ void dummy_kernel() {}   // launch-position filler for ncu -s 5

// ---------------------------------------------------------------------------
// xw[t][j][b] = sum_d X[b][t][d] * Wxh[d][j]
__global__ __launch_bounds__(256) void xw_kernel(const float* __restrict__ X,
                                                 const float* __restrict__ Wxh) {
    __shared__ __align__(16) float Xs[128 * 33];  // [dl][b], padded
    __shared__ __align__(16) float Ws[128 * 32];  // [dl][jj]
    int t  = blockIdx.x;
    int j0 = blockIdx.y * 32;
    int tid = threadIdx.x;
    int warp = tid >> 5, lane = tid & 31;
    float acc0 = 0.f, acc1 = 0.f, acc2 = 0.f, acc3 = 0.f;

    for (int kp = 0; kp < 2; ++kp) {
        #pragma unroll
        for (int bb = 0; bb < 4; ++bb) {
            int b = warp * 4 + bb;
            const float* xp = X + ((size_t)b * T_STEPS + t) * DIN + kp * 128;
            #pragma unroll
            for (int it = 0; it < 4; ++it) {
                int dl = it * 32 + lane;
                Xs[dl * 33 + b] = xp[dl];
            }
        }
        for (int idx = tid; idx < 128 * 32; idx += 256) {
            int dl = idx >> 5, jj = idx & 31;
            Ws[idx] = Wxh[(size_t)(kp * 128 + dl) * HDIM + j0 + jj];
        }
        __syncthreads();
        #pragma unroll 8
        for (int dl = 0; dl < 128; ++dl) {
            float xv = Xs[dl * 33 + lane];
            float4 w = *(const float4*)&Ws[dl * 32 + warp * 4];
            acc0 += xv * w.x; acc1 += xv * w.y; acc2 += xv * w.z; acc3 += xv * w.w;
        }
        __syncthreads();
    }
    float* op = g_xw + ((size_t)t * HDIM + j0 + warp * 4) * BATCH + lane;
    op[0]  = acc0;
    op[32] = acc1;
    op[64] = acc2;
    op[96] = acc3;
}

// ---------------------------------------------------------------------------
__device__ __forceinline__ unsigned smem_u32(const void* p) {
    unsigned a;
    asm("{ .reg .u64 t; cvta.to.shared.u64 t, %1; cvt.u32.u64 %0, t; }"
        : "=r"(a) : "l"(p));
    return a;
}

// Persistent recurrence, cluster-confined. 16 clusters x 8 CTAs; cluster owns
// a BATCH PAIR (batches are independent -> no grid-wide barrier, only
// cluster.sync + DSMEM exchange). CTA owns JSLICE=64 j's; Whh slice lives in
// REGISTERS (64 u64 j-pair-packed per thread; 256 threads = 32 jp x 8 i-ranges).
__global__ __launch_bounds__(RTHREADS) __cluster_dims__(CSIZE, 1, 1)
void rnn_loop(const float* __restrict__ Whh,
              const float* __restrict__ bh,
              float* __restrict__ Y) {
    __shared__ __align__(16) unsigned long long hdup[2][HDIM];  // [b][i] {h,h}, 8KB
    __shared__ __align__(16) unsigned long long red[2][8][32];  // [b][ig][jp], 4KB
    __shared__ __align__(16) float buf[2][JSLICE * 2];          // [parity][jl*2+b]

    int tid  = threadIdx.x;
    int warp = tid >> 5;        // ig: i-range = warp*64 .. +63
    int lane = tid & 31;        // jp: j-pair (jbase + 2*lane, +1)
    unsigned rank;
    asm("mov.u32 %0, %%cluster_ctarank;" : "=r"(rank));
    int cb    = blockIdx.x >> 3;            // cluster index = batch-pair 0..15
    int jbase = (int)rank * JSLICE;

    // ---- load Whh slice into registers: w64[k] = {W[i][j0], W[i][j1]} ----
    unsigned long long w64[64];
    {
        const float* wp = Whh + (size_t)(warp * 64) * HDIM + jbase + lane * 2;
        #pragma unroll
        for (int k = 0; k < 64; ++k) {
            float2 wv = *(const float2*)(wp + (size_t)k * HDIM);
            asm("mov.b64 %0, {%1, %2};" : "=l"(w64[k]) : "f"(wv.x), "f"(wv.y));
        }
    }

    // finisher mapping (tid < 128): fb = tid>>6 (batch in pair), fj = tid&63
    int fb = tid >> 6, fj = tid & 63;
    float bias = (tid < 128) ? bh[jbase + fj] : 0.f;
    float xw_pref = (tid < 128)
        ? g_xw[((size_t)0 * HDIM + jbase + fj) * BATCH + cb * 2 + fb] : 0.f;
    if (tid < 128) buf[0][tid] = 0.f;   // h(0) = 0

    // pull-phase mapping: entries e = tid*4..+3 -> (b = e>>9, i = e&511)
    asm volatile("barrier.cluster.arrive.aligned;" ::: "memory");
    asm volatile("barrier.cluster.wait.aligned;" ::: "memory");

    int p = 0;
    for (int t = 0; t < T_STEPS; ++t) {
        // ---- pull h from all ranks' buf[p] via DSMEM, build duplicated hdup ----
        #pragma unroll
        for (int q = 0; q < 4; ++q) {
            int e = tid * 4 + q;
            int b = e >> 9, i = e & 511;
            int r = i >> 6, jl = i & 63;
            unsigned laddr = smem_u32(&buf[p][jl * 2 + b]);
            unsigned raddr;
            float v;
            asm("mapa.shared::cluster.u32 %0, %1, %2;" : "=r"(raddr)
                : "r"(laddr), "r"(r));
            asm("ld.shared::cluster.f32 %0, [%1];" : "=f"(v) : "r"(raddr));
            unsigned long long v2;
            asm("mov.b64 %0, {%1, %1};" : "=l"(v2) : "f"(v));
            hdup[b][i] = v2;
        }
        __syncthreads();

        // ---- compute: acc over own 64-i range, both batches, j-pair packed ----
        unsigned long long acc0 = 0ull, acc1 = 0ull;
        {
            const ulonglong2* h0 = (const ulonglong2*)&hdup[0][warp * 64];
            const ulonglong2* h1 = (const ulonglong2*)&hdup[1][warp * 64];
            #pragma unroll
            for (int k = 0; k < 32; ++k) {
                ulonglong2 A = h0[k];
                ulonglong2 B = h1[k];
                asm("fma.rn.f32x2 %0, %1, %2, %0;" : "+l"(acc0) : "l"(A.x), "l"(w64[2*k]));
                asm("fma.rn.f32x2 %0, %1, %2, %0;" : "+l"(acc0) : "l"(A.y), "l"(w64[2*k+1]));
                asm("fma.rn.f32x2 %0, %1, %2, %0;" : "+l"(acc1) : "l"(B.x), "l"(w64[2*k]));
                asm("fma.rn.f32x2 %0, %1, %2, %0;" : "+l"(acc1) : "l"(B.y), "l"(w64[2*k+1]));
            }
        }
        red[0][warp][lane] = acc0;
        red[1][warp][lane] = acc1;
        __syncthreads();

        // ---- finish: reduce 8 i-ranges, tanh, publish locally ----
        if (tid < 128) {
            float s = bias + xw_pref;
            #pragma unroll
            for (int ig = 0; ig < 8; ++ig)
                s += ((const float*)&red[fb][ig][fj >> 1])[fj & 1];
            float hv = tanhf(s);
            buf[p ^ 1][fj * 2 + fb] = hv;
            Y[(size_t)t * (BATCH * HDIM) + (size_t)(cb * 2 + fb) * HDIM + jbase + fj] = hv;
            if (t + 1 < T_STEPS)
                xw_pref = g_xw[((size_t)(t + 1) * HDIM + jbase + fj) * BATCH + cb * 2 + fb];
        }

        // ---- one cluster barrier per step ----
        asm volatile("barrier.cluster.arrive.aligned;" ::: "memory");
        asm volatile("barrier.cluster.wait.aligned;" ::: "memory");
        p ^= 1;
    }
}

// ---------------------------------------------------------------------------
// Q0[b] = Y[T-1,b] @ QW ; Qh[b] = KW @ Q0[b]   (one CTA per b)
__global__ __launch_bounds__(256) void att_q_kernel(const float* __restrict__ Y,
                                                    const float* __restrict__ QW,
                                                    const float* __restrict__ KW) {
    __shared__ float yT[HDIM];
    __shared__ float q0s[DIN];
    int b = blockIdx.x, tid = threadIdx.x;
    for (int h = tid; h < HDIM; h += 256)
        yT[h] = Y[(size_t)(T_STEPS - 1) * BATCH * HDIM + (size_t)b * HDIM + h];
    __syncthreads();
    float s = 0.f;
    for (int h = 0; h < HDIM; ++h) s += yT[h] * QW[(size_t)h * DIN + tid];
    q0s[tid] = s;
    __syncthreads();
    for (int j = tid; j < HDIM; j += 256) {
        float s2 = 0.f;
        const float* kp = KW + (size_t)j * DIN;
        #pragma unroll 4
        for (int d = 0; d < DIN; ++d) s2 += kp[d] * q0s[d];
        g_qh[b * HDIM + j] = s2;
    }
}

// scores[b][t] = tanh( Y[t,b,:] . Qh[b,:] )
__global__ __launch_bounds__(256) void att_scores_kernel(const float* __restrict__ Y) {
    __shared__ float qh[HDIM];
    int b = blockIdx.y, t0 = blockIdx.x * 64, tid = threadIdx.x;
    for (int h = tid; h < HDIM; h += 256) qh[h] = g_qh[b * HDIM + h];
    __syncthreads();
    int warp = tid >> 5, lane = tid & 31;
    for (int tt = warp; tt < 64; tt += 8) {
        int t = t0 + tt;
        const float* yp = Y + (size_t)t * BATCH * HDIM + (size_t)b * HDIM;
        float s = 0.f;
        #pragma unroll
        for (int it = 0; it < 16; ++it) s += yp[it * 32 + lane] * qh[it * 32 + lane];
        #pragma unroll
        for (int off = 16; off > 0; off >>= 1) s += __shfl_xor_sync(0xffffffffu, s, off);
        if (lane == 0) g_sc[b * T_STEPS + t] = tanhf(s);
    }
}

__global__ __launch_bounds__(256) void att_softmax_kernel() {
    __shared__ float sred[256];
    int b = blockIdx.x, tid = threadIdx.x;
    const float* sp = g_sc + b * T_STEPS;
    float m = -1e30f;
    for (int t = tid; t < T_STEPS; t += 256) m = fmaxf(m, sp[t]);
    sred[tid] = m; __syncthreads();
    for (int o = 128; o > 0; o >>= 1) {
        if (tid < o) sred[tid] = fmaxf(sred[tid], sred[tid + o]);
        __syncthreads();
    }
    m = sred[0]; __syncthreads();
    float sum = 0.f;
    for (int t = tid; t < T_STEPS; t += 256) sum += expf(sp[t] - m);
    sred[tid] = sum; __syncthreads();
    for (int o = 128; o > 0; o >>= 1) {
        if (tid < o) sred[tid] += sred[tid + o];
        __syncthreads();
    }
    float inv = 1.f / sred[0];
    for (int t = tid; t < T_STEPS; t += 256)
        g_att[b * T_STEPS + t] = expf(sp[t] - m) * inv;
}

// c partials: grid (8 t-chunks, 32 b)
__global__ __launch_bounds__(256) void att_ctx_kernel(const float* __restrict__ Y) {
    __shared__ float As[256];
    int tc = blockIdx.x, b = blockIdx.y, tid = threadIdx.x;
    As[tid] = g_att[b * T_STEPS + tc * 256 + tid];
    __syncthreads();
    float acc0 = 0.f, acc1 = 0.f;
    for (int tt = 0; tt < 256; ++tt) {
        const float* yp = Y + (size_t)(tc * 256 + tt) * BATCH * HDIM + (size_t)b * HDIM;
        float a = As[tt];
        acc0 += a * yp[tid];
        acc1 += a * yp[tid + 256];
    }
    g_cpart[tc][b * HDIM + tid]        = acc0;
    g_cpart[tc][b * HDIM + tid + 256]  = acc1;
}

__global__ __launch_bounds__(512) void att_ctx2_kernel(float* __restrict__ out_c) {
    int b = blockIdx.x, tid = threadIdx.x;
    float s = 0.f;
    #pragma unroll
    for (int p = 0; p < 8; ++p) s += g_cpart[p][b * HDIM + tid];
    out_c[(size_t)b * HDIM + tid] = s;
}

// ---------------------------------------------------------------------------
extern "C" void kernel_launch(void* const* d_in, const int* in_sizes, int n_in,
                              void* d_out, int out_size) {
    const float* X   = (const float*)d_in[0];
    const float* Wxh = (const float*)d_in[1];
    const float* Whh = (const float*)d_in[2];
    const float* bh  = (const float*)d_in[3];
    const float* QW  = (const float*)d_in[4];
    const float* KW  = (const float*)d_in[5];
    float* Y = (float*)d_out;                                    // [T][B][H]
    float* out_c = Y + (size_t)T_STEPS * BATCH * HDIM;           // [B][H]

    init_kernel<<<64, 256>>>();
    xw_kernel<<<dim3(T_STEPS, 16), 256>>>(X, Wxh);
    dummy_kernel<<<1, 32>>>();     // position rnn_loop at the ncu capture slot
    rnn_loop<<<16 * CSIZE, RTHREADS>>>(Whh, bh, Y);
    att_q_kernel<<<BATCH, 256>>>(Y, QW, KW);
    att_scores_kernel<<<dim3(32, BATCH), 256>>>(Y);
    att_softmax_kernel<<<BATCH, 256>>>();
    att_ctx_kernel<<<dim3(8, BATCH), 256>>>(Y);
    att_ctx2_kernel<<<BATCH, 512>>>(out_c);
}